// round 10
// baseline (speedup 1.0000x reference)
#include <cuda_runtime.h>

#define NN 50000
#define HD 128
#define EMAX 1700000
#define TILE 64            // dst-nodes per fused block (16 warps x 4 nodes)

// ---------------- scratch (device globals; no allocation allowed) ----------
__device__ float g_bufA[NN * HD];   // X@W1 (raw)
__device__ float g_bufB[NN * HD];   // A2 = (h1@W2)*dinv
__device__ float g_bufU[NN * HD];   // U = h2 @ Wh1_top
__device__ float g_bufV[NN * HD];   // V = h2 @ Wh1_bot
__device__ int   g_deg[NN];
__device__ float g_dinv[NN];
__device__ int   g_ptr[NN + 1];
__device__ int   g_cur[NN];
__device__ int   g_srcs[EMAX];

// ---------------- CSR build ------------------------------------------------
__global__ void k_zero_deg() {
    int i = blockIdx.x * blockDim.x + threadIdx.x;
    if (i < NN) g_deg[i] = 0;
}

__global__ void k_hist(const int* __restrict__ ei, int E) {
    int e = blockIdx.x * blockDim.x + threadIdx.x;
    if (e < E) atomicAdd(&g_deg[ei[E + e]], 1);   // dst row of edge_index
}

// single-block exclusive scan over 50000 degrees; also dinv = rsqrt(deg+1)
__global__ void k_scan() {
    __shared__ int s[1024];
    int t = threadIdx.x;
    const int CH = (NN + 1023) / 1024;            // 49
    int st = t * CH;
    int en = min(st + CH, NN);
    int sum = 0;
    for (int i = st; i < en; i++) sum += g_deg[i];
    s[t] = sum;
    __syncthreads();
    for (int off = 1; off < 1024; off <<= 1) {
        int v = (t >= off) ? s[t - off] : 0;
        __syncthreads();
        s[t] += v;
        __syncthreads();
    }
    int base = (t == 0) ? 0 : s[t - 1];
    for (int i = st; i < en; i++) {
        int d = g_deg[i];
        g_ptr[i] = base;
        g_cur[i] = base;
        g_dinv[i] = rsqrtf((float)(d + 1));       // +1 = self loop
        base += d;
    }
    if (t == 1023) g_ptr[NN] = base;
}

__global__ void k_fill(const int* __restrict__ ei, int E) {
    int e = blockIdx.x * blockDim.x + threadIdx.x;
    if (e < E) {
        int d = ei[E + e];
        int pos = atomicAdd(&g_cur[d], 1);
        if (pos < EMAX) g_srcs[pos] = ei[e];
    }
}

// ---------------- GEMM1: Out[r] = X[r] @ W (raw) ---------------------------
#define GEMM_SMEM ((HD * HD + 32 * HD) * 4)

__global__ __launch_bounds__(256) void k_gemm(
    const float* __restrict__ X, const float* __restrict__ W,
    float* __restrict__ Out)
{
    extern __shared__ float sm[];
    float* sW = sm;                 // 128x128
    float* sX = sm + HD * HD;       // 32x128
    int tid = threadIdx.x;

    float4* sW4 = (float4*)sW;
    const float4* W4 = (const float4*)W;
    for (int i = tid; i < HD * HD / 4; i += 256) sW4[i] = W4[i];

    int row0 = blockIdx.x * 32;
    int nr = min(32, NN - row0);
    const float4* X4 = (const float4*)(X + (size_t)row0 * HD);
    float4* sX4 = (float4*)sX;
    for (int i = tid; i < nr * (HD / 4); i += 256) sX4[i] = X4[i];
    __syncthreads();

    int tx = tid & 31;
    int ty = tid >> 5;
    float4 acc[4];
    acc[0] = acc[1] = acc[2] = acc[3] = make_float4(0.f, 0.f, 0.f, 0.f);

#pragma unroll 4
    for (int k = 0; k < HD; k++) {
        float4 w = sW4[k * (HD / 4) + tx];
#pragma unroll
        for (int r = 0; r < 4; r++) {
            float xv = sX[(ty + r * 8) * HD + k];
            acc[r].x += xv * w.x;
            acc[r].y += xv * w.y;
            acc[r].z += xv * w.z;
            acc[r].w += xv * w.w;
        }
    }

#pragma unroll
    for (int r = 0; r < 4; r++) {
        int row = ty + r * 8;
        if (row < nr) {
            int grow = row0 + row;
            ((float4*)(Out + (size_t)grow * HD))[tx] = acc[r];
        }
    }
}

// ---------------- fused1: SpMM(layer1) + GEMM(W2), per 64-node tile --------
// phase1: h1[d] = relu( dinv[d]*(self*dinv[d]... ) + b1 ) with dinv[src]
//         applied at gather (HS is raw X@W1) -> smem
// phase2: Out[d] = (h1[d] @ W2) * dinv[d]
#define F1_SMEM ((HD * HD + TILE * HD) * 4)   // 64KB + 32KB

__global__ __launch_bounds__(512) void k_fused1(
    const float* __restrict__ HS, const float* __restrict__ bias,
    const float* __restrict__ W2, float* __restrict__ Out)
{
    extern __shared__ float sm[];
    float* sW = sm;                 // W2 128x128
    float* sH = sm + HD * HD;       // 64x128 gathered tile
    int tid = threadIdx.x;
    int lane = tid & 31;
    int w = tid >> 5;               // 0..15

    float4* sW4 = (float4*)sW;
    const float4* W4 = (const float4*)W2;
    for (int i = tid; i < HD * HD / 4; i += 512) sW4[i] = W4[i];

    int base = blockIdx.x * TILE;
    const float4* hs4 = (const float4*)HS;
    float4 bvec = ((const float4*)bias)[lane];

    // phase 1: each warp gathers 4 nodes
#pragma unroll
    for (int q = 0; q < 4; q++) {
        int node = base + w * 4 + q;
        if (node < NN) {
            float di = g_dinv[node];
            float4 acc = hs4[(size_t)node * 32 + lane];
            acc.x *= di; acc.y *= di; acc.z *= di; acc.w *= di;
            int p0 = g_ptr[node], p1 = g_ptr[node + 1];

            int e = p0;
            for (; e + 32 <= p1; e += 32) {
                int idx = g_srcs[e + lane];
                float dv = g_dinv[idx];
#pragma unroll
                for (int j = 0; j < 32; j++) {
                    int s = __shfl_sync(0xffffffffu, idx, j);
                    float ds = __shfl_sync(0xffffffffu, dv, j);
                    float4 v = hs4[(size_t)s * 32 + lane];
                    acc.x = fmaf(v.x, ds, acc.x);
                    acc.y = fmaf(v.y, ds, acc.y);
                    acc.z = fmaf(v.z, ds, acc.z);
                    acc.w = fmaf(v.w, ds, acc.w);
                }
            }
            if (e < p1) {
                int m = p1 - e;
                int idx = (lane < m) ? g_srcs[e + lane] : 0;
                float dv = (lane < m) ? g_dinv[idx] : 0.f;
                for (int j = 0; j < m; j++) {
                    int s = __shfl_sync(0xffffffffu, idx, j);
                    float ds = __shfl_sync(0xffffffffu, dv, j);
                    float4 v = hs4[(size_t)s * 32 + lane];
                    acc.x = fmaf(v.x, ds, acc.x);
                    acc.y = fmaf(v.y, ds, acc.y);
                    acc.z = fmaf(v.z, ds, acc.z);
                    acc.w = fmaf(v.w, ds, acc.w);
                }
            }
            float4 o;
            o.x = fmaxf(fmaf(acc.x, di, bvec.x), 0.f);
            o.y = fmaxf(fmaf(acc.y, di, bvec.y), 0.f);
            o.z = fmaxf(fmaf(acc.z, di, bvec.z), 0.f);
            o.w = fmaxf(fmaf(acc.w, di, bvec.w), 0.f);
            ((float4*)(sH + (w * 4 + q) * HD))[lane] = o;
        }
    }
    __syncthreads();

    // phase 2: 64 rows x 128 cols GEMM from smem
    int tx = lane;
    float4 acc[4];
    acc[0] = acc[1] = acc[2] = acc[3] = make_float4(0.f, 0.f, 0.f, 0.f);
#pragma unroll 4
    for (int k = 0; k < HD; k++) {
        float4 wv = sW4[k * 32 + tx];
#pragma unroll
        for (int r = 0; r < 4; r++) {
            float xv = sH[(w + r * 16) * HD + k];
            acc[r].x += xv * wv.x;
            acc[r].y += xv * wv.y;
            acc[r].z += xv * wv.z;
            acc[r].w += xv * wv.w;
        }
    }
#pragma unroll
    for (int r = 0; r < 4; r++) {
        int grow = base + w + r * 16;
        if (grow < NN) {
            float di = g_dinv[grow];
            float4 v = make_float4(acc[r].x * di, acc[r].y * di,
                                   acc[r].z * di, acc[r].w * di);
            ((float4*)(Out + (size_t)grow * HD))[tx] = v;
        }
    }
}

// ---------------- fused2: SpMM(layer2) + U/V GEMM (Wh1) --------------------
// phase1: h2[d] = relu( dinv[d]*(self + sum A2[s]) + b2 )  (A2 pre-scaled)
// phase2: U[d] = h2[d] @ Wh1_top ; V[d] = h2[d] @ Wh1_bot
#define F2_SMEM ((2 * HD * HD + TILE * HD) * 4)   // 128KB + 32KB

__global__ __launch_bounds__(512) void k_fused2(
    const float* __restrict__ HS, const float* __restrict__ bias,
    const float* __restrict__ Wh1,
    float* __restrict__ U, float* __restrict__ V)
{
    extern __shared__ float sm[];
    float* sWU = sm;                     // Wh1 top 128x128
    float* sWV = sm + HD * HD;           // Wh1 bottom 128x128
    float* sH  = sm + 2 * HD * HD;       // 64x128 tile
    int tid = threadIdx.x;
    int lane = tid & 31;
    int w = tid >> 5;

    float4* sWU4 = (float4*)sWU;
    float4* sWV4 = (float4*)sWV;
    const float4* WU4 = (const float4*)Wh1;
    const float4* WV4 = (const float4*)(Wh1 + HD * HD);
    for (int i = tid; i < HD * HD / 4; i += 512) {
        sWU4[i] = WU4[i];
        sWV4[i] = WV4[i];
    }

    int base = blockIdx.x * TILE;
    const float4* hs4 = (const float4*)HS;
    float4 bvec = ((const float4*)bias)[lane];

    // phase 1
#pragma unroll
    for (int q = 0; q < 4; q++) {
        int node = base + w * 4 + q;
        if (node < NN) {
            float di = g_dinv[node];
            float4 acc = hs4[(size_t)node * 32 + lane];   // self (pre-scaled)
            int p0 = g_ptr[node], p1 = g_ptr[node + 1];

            int e = p0;
            for (; e + 32 <= p1; e += 32) {
                int idx = g_srcs[e + lane];
#pragma unroll
                for (int j = 0; j < 32; j++) {
                    int s = __shfl_sync(0xffffffffu, idx, j);
                    float4 v = hs4[(size_t)s * 32 + lane];
                    acc.x += v.x; acc.y += v.y; acc.z += v.z; acc.w += v.w;
                }
            }
            if (e < p1) {
                int m = p1 - e;
                int idx = (lane < m) ? g_srcs[e + lane] : 0;
                for (int j = 0; j < m; j++) {
                    int s = __shfl_sync(0xffffffffu, idx, j);
                    float4 v = hs4[(size_t)s * 32 + lane];
                    acc.x += v.x; acc.y += v.y; acc.z += v.z; acc.w += v.w;
                }
            }
            float4 o;
            o.x = fmaxf(fmaf(acc.x, di, bvec.x), 0.f);
            o.y = fmaxf(fmaf(acc.y, di, bvec.y), 0.f);
            o.z = fmaxf(fmaf(acc.z, di, bvec.z), 0.f);
            o.w = fmaxf(fmaf(acc.w, di, bvec.w), 0.f);
            ((float4*)(sH + (w * 4 + q) * HD))[lane] = o;
        }
    }
    __syncthreads();

    // phase 2: 64 rows x (128 U-cols + 128 V-cols)
    int tx = lane;
    float4 aU[4], aV[4];
#pragma unroll
    for (int r = 0; r < 4; r++) {
        aU[r] = make_float4(0.f, 0.f, 0.f, 0.f);
        aV[r] = make_float4(0.f, 0.f, 0.f, 0.f);
    }
#pragma unroll 2
    for (int k = 0; k < HD; k++) {
        float4 wu = sWU4[k * 32 + tx];
        float4 wv = sWV4[k * 32 + tx];
#pragma unroll
        for (int r = 0; r < 4; r++) {
            float xv = sH[(w + r * 16) * HD + k];
            aU[r].x += xv * wu.x; aU[r].y += xv * wu.y;
            aU[r].z += xv * wu.z; aU[r].w += xv * wu.w;
            aV[r].x += xv * wv.x; aV[r].y += xv * wv.y;
            aV[r].z += xv * wv.z; aV[r].w += xv * wv.w;
        }
    }
#pragma unroll
    for (int r = 0; r < 4; r++) {
        int grow = base + w + r * 16;
        if (grow < NN) {
            ((float4*)(U + (size_t)grow * HD))[tx] = aU[r];
            ((float4*)(V + (size_t)grow * HD))[tx] = aV[r];
        }
    }
}

// ---------------- pair epilogue --------------------------------------------
// out[p] = relu(U[p0] + V[p1] + bh1) . Wh2 + bh2
__global__ __launch_bounds__(256) void k_pair(
    const int* __restrict__ pairs,
    const float* __restrict__ bh1, const float* __restrict__ Wh2,
    const float* __restrict__ bh2,
    float* __restrict__ out, int P)
{
    int gw = (blockIdx.x * blockDim.x + threadIdx.x) >> 5;
    int lane = threadIdx.x & 31;
    if (gw >= P) return;

    int n0 = pairs[2 * gw];
    int n1 = pairs[2 * gw + 1];

    const float4* U4 = (const float4*)g_bufU;
    const float4* V4 = (const float4*)g_bufV;
    float4 u = U4[(size_t)n0 * 32 + lane];
    float4 v = V4[(size_t)n1 * 32 + lane];
    float4 b = ((const float4*)bh1)[lane];
    float4 w = ((const float4*)Wh2)[lane];

    float s = fmaxf(u.x + v.x + b.x, 0.f) * w.x
            + fmaxf(u.y + v.y + b.y, 0.f) * w.y
            + fmaxf(u.z + v.z + b.z, 0.f) * w.z
            + fmaxf(u.w + v.w + b.w, 0.f) * w.w;
#pragma unroll
    for (int o = 16; o > 0; o >>= 1)
        s += __shfl_xor_sync(0xffffffffu, s, o);
    if (lane == 0) out[gw] = s + bh2[0];
}

// ---------------- launch ---------------------------------------------------
extern "C" void kernel_launch(void* const* d_in, const int* in_sizes, int n_in,
                              void* d_out, int out_size)
{
    const float* x    = (const float*)d_in[0];
    const int*   ei   = (const int*)d_in[1];
    const int*   prs  = (const int*)d_in[2];
    const float* W1   = (const float*)d_in[3];
    const float* b1   = (const float*)d_in[4];
    const float* W2   = (const float*)d_in[5];
    const float* b2   = (const float*)d_in[6];
    const float* Wh1  = (const float*)d_in[7];
    const float* bh1  = (const float*)d_in[8];
    const float* Wh2  = (const float*)d_in[9];
    const float* bh2  = (const float*)d_in[10];
    float* out = (float*)d_out;

    int E = in_sizes[1] / 2;
    int P = in_sizes[2] / 2;

    // one-time host objects (no device memory involved)
    static cudaStream_t s2 = []() {
        cudaStream_t s;
        cudaStreamCreateWithFlags(&s, cudaStreamNonBlocking);
        return s;
    }();
    static cudaEvent_t evFork = []() {
        cudaEvent_t e;
        cudaEventCreateWithFlags(&e, cudaEventDisableTiming);
        return e;
    }();
    static cudaEvent_t evJoin = []() {
        cudaEvent_t e;
        cudaEventCreateWithFlags(&e, cudaEventDisableTiming);
        return e;
    }();

    cudaFuncSetAttribute(k_gemm,
                         cudaFuncAttributeMaxDynamicSharedMemorySize, GEMM_SMEM);
    cudaFuncSetAttribute(k_fused1,
                         cudaFuncAttributeMaxDynamicSharedMemorySize, F1_SMEM);
    cudaFuncSetAttribute(k_fused2,
                         cudaFuncAttributeMaxDynamicSharedMemorySize, F2_SMEM);

    void *pA = nullptr, *pB = nullptr, *pU = nullptr, *pV = nullptr;
    cudaGetSymbolAddress(&pA, g_bufA);
    cudaGetSymbolAddress(&pB, g_bufB);
    cudaGetSymbolAddress(&pU, g_bufU);
    cudaGetSymbolAddress(&pV, g_bufV);
    float* A = (float*)pA;
    float* B = (float*)pB;
    float* U = (float*)pU;
    float* V = (float*)pV;

    const int GB = (NN + 31) / 32;
    const int FB = (NN + TILE - 1) / TILE;

    // fork: CSR build chain on s2, concurrent with GEMM1 on main stream
    cudaEventRecord(evFork, 0);
    cudaStreamWaitEvent(s2, evFork, 0);

    k_zero_deg<<<(NN + 255) / 256, 256, 0, s2>>>();
    k_hist<<<(E + 255) / 256, 256, 0, s2>>>(ei, E);
    k_scan<<<1, 1024, 0, s2>>>();
    k_fill<<<(E + 255) / 256, 256, 0, s2>>>(ei, E);

    // GEMM1 (raw X@W1 — no dinv dependency, overlaps CSR build)
    k_gemm<<<GB, 256, GEMM_SMEM>>>(x, W1, A);

    // join
    cudaEventRecord(evJoin, s2);
    cudaStreamWaitEvent(0, evJoin, 0);

    // fused layer1-aggregation + W2 transform
    k_fused1<<<FB, 512, F1_SMEM>>>(A, b1, W2, B);
    // fused layer2-aggregation + U/V head transform
    k_fused2<<<FB, 512, F2_SMEM>>>(B, b2, Wh1, U, V);
    // pair epilogue
    k_pair<<<(P * 32 + 255) / 256, 256>>>(prs, bh1, Wh2, bh2, out, P);
}

// round 11
// speedup vs baseline: 1.0833x; 1.0833x over previous
#include <cuda_runtime.h>

#define NN 50000
#define HD 128
#define EMAX 1700000

// ---------------- scratch (device globals; no allocation allowed) ----------
__device__ float g_bufA[NN * HD];   // X@W1 (raw) / (h1@W2)*dinv
__device__ float g_bufB[NN * HD];   // layer activations
__device__ float g_bufU[NN * HD];   // U = h2 @ Wh1_top
__device__ float g_bufV[NN * HD];   // V = h2 @ Wh1_bot
__device__ int   g_deg[NN];
__device__ float g_dinv[NN];
__device__ int   g_ptr[NN + 1];
__device__ int   g_cur[NN];
__device__ int   g_srcs[EMAX];

// ---------------- CSR build ------------------------------------------------
__global__ void k_zero_deg() {
    int i = blockIdx.x * blockDim.x + threadIdx.x;
    if (i < NN) g_deg[i] = 0;
}

__global__ void k_hist(const int* __restrict__ ei, int E) {
    int e = blockIdx.x * blockDim.x + threadIdx.x;
    if (e < E) atomicAdd(&g_deg[ei[E + e]], 1);   // dst row of edge_index
}

// single-block exclusive scan over 50000 degrees; also dinv = rsqrt(deg+1)
__global__ void k_scan() {
    __shared__ int s[1024];
    int t = threadIdx.x;
    const int CH = (NN + 1023) / 1024;            // 49
    int st = t * CH;
    int en = min(st + CH, NN);
    int sum = 0;
    for (int i = st; i < en; i++) sum += g_deg[i];
    s[t] = sum;
    __syncthreads();
    for (int off = 1; off < 1024; off <<= 1) {
        int v = (t >= off) ? s[t - off] : 0;
        __syncthreads();
        s[t] += v;
        __syncthreads();
    }
    int base = (t == 0) ? 0 : s[t - 1];
    for (int i = st; i < en; i++) {
        int d = g_deg[i];
        g_ptr[i] = base;
        g_cur[i] = base;
        g_dinv[i] = rsqrtf((float)(d + 1));       // +1 = self loop
        base += d;
    }
    if (t == 1023) g_ptr[NN] = base;
}

__global__ void k_fill(const int* __restrict__ ei, int E) {
    int e = blockIdx.x * blockDim.x + threadIdx.x;
    if (e < E) {
        int d = ei[E + e];
        int pos = atomicAdd(&g_cur[d], 1);
        if (pos < EMAX) g_srcs[pos] = ei[e];
    }
}

// ---------------- register-blocked GEMM ------------------------------------
// 64 rows x 128 cols per block, 256 threads, thread = 8 rows x 4 cols.
// Per warp-k: 1 LDS128 (w) + 8 LDS32 broadcasts vs 32 FFMA-instr
// -> crossbar at 75% of fma, fma-pipe is the sole bottleneck.
#define GEMM_RB_SMEM ((HD * HD + 64 * HD) * 4)    // 64KB + 32KB

template <bool SCALE>
__global__ __launch_bounds__(256) void k_gemm_rb(
    const float* __restrict__ X, const float* __restrict__ W,
    float* __restrict__ Out)
{
    extern __shared__ float sm[];
    float* sW = sm;                 // 128x128
    float* sX = sm + HD * HD;       // 64x128
    int tid = threadIdx.x;

    float4* sW4 = (float4*)sW;
    const float4* W4 = (const float4*)W;
    for (int i = tid; i < HD * HD / 4; i += 256) sW4[i] = W4[i];

    int row0 = blockIdx.x * 64;
    int nr = min(64, NN - row0);
    const float4* X4 = (const float4*)(X + (size_t)row0 * HD);
    float4* sX4 = (float4*)sX;
    for (int i = tid; i < nr * (HD / 4); i += 256) sX4[i] = X4[i];
    __syncthreads();

    int tx = tid & 31;              // float4-col index (cols tx*4..tx*4+3)
    int rg = tid >> 5;              // row group 0..7 -> rows rg*8..rg*8+7
    const float* xrow = sX + rg * 8 * HD;

    float4 acc[8];
#pragma unroll
    for (int r = 0; r < 8; r++) acc[r] = make_float4(0.f, 0.f, 0.f, 0.f);

#pragma unroll 4
    for (int k = 0; k < HD; k++) {
        float4 w = sW4[k * 32 + tx];
#pragma unroll
        for (int r = 0; r < 8; r++) {
            float xv = xrow[r * HD + k];            // warp-uniform broadcast
            acc[r].x += xv * w.x;
            acc[r].y += xv * w.y;
            acc[r].z += xv * w.z;
            acc[r].w += xv * w.w;
        }
    }

#pragma unroll
    for (int r = 0; r < 8; r++) {
        int lrow = rg * 8 + r;
        if (lrow < nr) {
            int grow = row0 + lrow;
            float s = SCALE ? g_dinv[grow] : 1.0f;
            float4 v = make_float4(acc[r].x * s, acc[r].y * s,
                                   acc[r].z * s, acc[r].w * s);
            ((float4*)(Out + (size_t)grow * HD))[tx] = v;
        }
    }
}

// merged U/V GEMM: blockIdx.y picks Wh1 half / output buffer
__global__ __launch_bounds__(256) void k_gemm_uv(
    const float* __restrict__ X, const float* __restrict__ Wh1,
    float* __restrict__ U, float* __restrict__ V)
{
    extern __shared__ float sm[];
    float* sW = sm;
    float* sX = sm + HD * HD;
    int tid = threadIdx.x;
    const float* W = Wh1 + (size_t)blockIdx.y * HD * HD;
    float* Out = blockIdx.y ? V : U;

    float4* sW4 = (float4*)sW;
    const float4* W4 = (const float4*)W;
    for (int i = tid; i < HD * HD / 4; i += 256) sW4[i] = W4[i];

    int row0 = blockIdx.x * 64;
    int nr = min(64, NN - row0);
    const float4* X4 = (const float4*)(X + (size_t)row0 * HD);
    float4* sX4 = (float4*)sX;
    for (int i = tid; i < nr * (HD / 4); i += 256) sX4[i] = X4[i];
    __syncthreads();

    int tx = tid & 31;
    int rg = tid >> 5;
    const float* xrow = sX + rg * 8 * HD;

    float4 acc[8];
#pragma unroll
    for (int r = 0; r < 8; r++) acc[r] = make_float4(0.f, 0.f, 0.f, 0.f);

#pragma unroll 4
    for (int k = 0; k < HD; k++) {
        float4 w = sW4[k * 32 + tx];
#pragma unroll
        for (int r = 0; r < 8; r++) {
            float xv = xrow[r * HD + k];
            acc[r].x += xv * w.x;
            acc[r].y += xv * w.y;
            acc[r].z += xv * w.z;
            acc[r].w += xv * w.w;
        }
    }

#pragma unroll
    for (int r = 0; r < 8; r++) {
        int lrow = rg * 8 + r;
        if (lrow < nr) {
            int grow = row0 + lrow;
            ((float4*)(Out + (size_t)grow * HD))[tx] = acc[r];
        }
    }
}

// ---------------- SpMM: warp per dst node, pull-based, no atomics ----------
// SRCSCALE=true : HS is raw X@W; gathered rows scaled by dinv[src] on the fly.
// SRCSCALE=false: HS already scaled by dinv (GEMM epilogue).
// Out[d] = relu( dinv[d] * (self + sum) + bias )
template <bool SRCSCALE>
__global__ __launch_bounds__(256) void k_spmm(
    const float* __restrict__ HS, const float* __restrict__ bias,
    float* __restrict__ Out)
{
    int gw = (blockIdx.x * blockDim.x + threadIdx.x) >> 5;
    int lane = threadIdx.x & 31;
    if (gw >= NN) return;

    float di = g_dinv[gw];
    const float4* hs4 = (const float4*)HS;
    float4 self = hs4[(size_t)gw * 32 + lane];
    float4 acc;
    if (SRCSCALE) {
        acc.x = self.x * di; acc.y = self.y * di;
        acc.z = self.z * di; acc.w = self.w * di;
    } else {
        acc = self;
    }
    int p0 = g_ptr[gw], p1 = g_ptr[gw + 1];

    int e = p0;
    for (; e + 32 <= p1; e += 32) {
        int idx = g_srcs[e + lane];
        float dv = SRCSCALE ? g_dinv[idx] : 0.f;
#pragma unroll
        for (int j = 0; j < 32; j++) {
            int s = __shfl_sync(0xffffffffu, idx, j);
            float4 v = hs4[(size_t)s * 32 + lane];
            if (SRCSCALE) {
                float ds = __shfl_sync(0xffffffffu, dv, j);
                acc.x = fmaf(v.x, ds, acc.x);
                acc.y = fmaf(v.y, ds, acc.y);
                acc.z = fmaf(v.z, ds, acc.z);
                acc.w = fmaf(v.w, ds, acc.w);
            } else {
                acc.x += v.x; acc.y += v.y; acc.z += v.z; acc.w += v.w;
            }
        }
    }
    if (e < p1) {
        int m = p1 - e;
        int idx = (lane < m) ? g_srcs[e + lane] : 0;
        float dv = SRCSCALE ? ((lane < m) ? g_dinv[idx] : 0.f) : 0.f;
        for (int j = 0; j < m; j++) {
            int s = __shfl_sync(0xffffffffu, idx, j);
            float4 v = hs4[(size_t)s * 32 + lane];
            if (SRCSCALE) {
                float ds = __shfl_sync(0xffffffffu, dv, j);
                acc.x = fmaf(v.x, ds, acc.x);
                acc.y = fmaf(v.y, ds, acc.y);
                acc.z = fmaf(v.z, ds, acc.z);
                acc.w = fmaf(v.w, ds, acc.w);
            } else {
                acc.x += v.x; acc.y += v.y; acc.z += v.z; acc.w += v.w;
            }
        }
    }

    float4 b = ((const float4*)bias)[lane];
    float4 o;
    o.x = fmaxf(fmaf(acc.x, di, b.x), 0.f);
    o.y = fmaxf(fmaf(acc.y, di, b.y), 0.f);
    o.z = fmaxf(fmaf(acc.z, di, b.z), 0.f);
    o.w = fmaxf(fmaf(acc.w, di, b.w), 0.f);
    ((float4*)Out)[(size_t)gw * 32 + lane] = o;
}

// ---------------- pair epilogue --------------------------------------------
// out[p] = relu(U[p0] + V[p1] + bh1) . Wh2 + bh2
__global__ __launch_bounds__(256) void k_pair(
    const int* __restrict__ pairs,
    const float* __restrict__ bh1, const float* __restrict__ Wh2,
    const float* __restrict__ bh2,
    float* __restrict__ out, int P)
{
    int gw = (blockIdx.x * blockDim.x + threadIdx.x) >> 5;
    int lane = threadIdx.x & 31;
    if (gw >= P) return;

    int n0 = pairs[2 * gw];
    int n1 = pairs[2 * gw + 1];

    const float4* U4 = (const float4*)g_bufU;
    const float4* V4 = (const float4*)g_bufV;
    float4 u = U4[(size_t)n0 * 32 + lane];
    float4 v = V4[(size_t)n1 * 32 + lane];
    float4 b = ((const float4*)bh1)[lane];
    float4 w = ((const float4*)Wh2)[lane];

    float s = fmaxf(u.x + v.x + b.x, 0.f) * w.x
            + fmaxf(u.y + v.y + b.y, 0.f) * w.y
            + fmaxf(u.z + v.z + b.z, 0.f) * w.z
            + fmaxf(u.w + v.w + b.w, 0.f) * w.w;
#pragma unroll
    for (int o = 16; o > 0; o >>= 1)
        s += __shfl_xor_sync(0xffffffffu, s, o);
    if (lane == 0) out[gw] = s + bh2[0];
}

// ---------------- launch ---------------------------------------------------
extern "C" void kernel_launch(void* const* d_in, const int* in_sizes, int n_in,
                              void* d_out, int out_size)
{
    const float* x    = (const float*)d_in[0];
    const int*   ei   = (const int*)d_in[1];
    const int*   prs  = (const int*)d_in[2];
    const float* W1   = (const float*)d_in[3];
    const float* b1   = (const float*)d_in[4];
    const float* W2   = (const float*)d_in[5];
    const float* b2   = (const float*)d_in[6];
    const float* Wh1  = (const float*)d_in[7];
    const float* bh1  = (const float*)d_in[8];
    const float* Wh2  = (const float*)d_in[9];
    const float* bh2  = (const float*)d_in[10];
    float* out = (float*)d_out;

    int E = in_sizes[1] / 2;
    int P = in_sizes[2] / 2;

    // one-time host objects (no device memory involved)
    static cudaStream_t s2 = []() {
        cudaStream_t s;
        cudaStreamCreateWithFlags(&s, cudaStreamNonBlocking);
        return s;
    }();
    static cudaEvent_t evFork = []() {
        cudaEvent_t e;
        cudaEventCreateWithFlags(&e, cudaEventDisableTiming);
        return e;
    }();
    static cudaEvent_t evJoin = []() {
        cudaEvent_t e;
        cudaEventCreateWithFlags(&e, cudaEventDisableTiming);
        return e;
    }();

    cudaFuncSetAttribute(k_gemm_rb<true>,
                         cudaFuncAttributeMaxDynamicSharedMemorySize, GEMM_RB_SMEM);
    cudaFuncSetAttribute(k_gemm_rb<false>,
                         cudaFuncAttributeMaxDynamicSharedMemorySize, GEMM_RB_SMEM);
    cudaFuncSetAttribute(k_gemm_uv,
                         cudaFuncAttributeMaxDynamicSharedMemorySize, GEMM_RB_SMEM);

    void *pA = nullptr, *pB = nullptr, *pU = nullptr, *pV = nullptr;
    cudaGetSymbolAddress(&pA, g_bufA);
    cudaGetSymbolAddress(&pB, g_bufB);
    cudaGetSymbolAddress(&pU, g_bufU);
    cudaGetSymbolAddress(&pV, g_bufV);
    float* A = (float*)pA;
    float* B = (float*)pB;
    float* U = (float*)pU;
    float* V = (float*)pV;

    const int GB = (NN + 63) / 64;

    // fork: CSR build chain on s2, concurrent with GEMM1 on main stream.
    // Launch order puts GEMM1 at position 4 so ncu's fixed skip window
    // profiles the GEMM instead of k_fill.
    cudaEventRecord(evFork, 0);
    cudaStreamWaitEvent(s2, evFork, 0);

    k_zero_deg<<<(NN + 255) / 256, 256, 0, s2>>>();
    k_hist<<<(E + 255) / 256, 256, 0, s2>>>(ei, E);
    k_scan<<<1, 1024, 0, s2>>>();

    // GEMM1 (raw X@W1 — no dinv dependency, overlaps CSR build)
    k_gemm_rb<false><<<GB, 256, GEMM_RB_SMEM>>>(x, W1, A);

    k_fill<<<(E + 255) / 256, 256, 0, s2>>>(ei, E);

    // join
    cudaEventRecord(evJoin, s2);
    cudaStreamWaitEvent(0, evJoin, 0);

    // layer 1 aggregation: dinv[src] applied at gather time
    k_spmm<true><<<(NN * 32 + 255) / 256, 256>>>(A, b1, B);
    // layer 2
    k_gemm_rb<true><<<GB, 256, GEMM_RB_SMEM>>>(B, W2, A);
    k_spmm<false><<<(NN * 32 + 255) / 256, 256>>>(A, b2, B);
    // factored pair-MLP head: U and V in one launch
    dim3 guv(GB, 2);
    k_gemm_uv<<<guv, 256, GEMM_RB_SMEM>>>(B, Wh1, U, V);
    // pair epilogue
    k_pair<<<(P * 32 + 255) / 256, 256>>>(prs, bh1, Wh2, bh2, out, P);
}

// round 15
// speedup vs baseline: 1.1177x; 1.0318x over previous
#include <cuda_runtime.h>

#define NN 50000
#define HD 128
#define EMAX 1700000

// ---------------- scratch (device globals; no allocation allowed) ----------
__device__ float g_bufA[NN * HD];   // X@W1 (raw) / (h1@W2)*dinv
__device__ float g_bufB[NN * HD];   // layer activations
__device__ float g_bufU[NN * HD];   // U = h2 @ Wh1_top
__device__ float g_bufV[NN * HD];   // V = h2 @ Wh1_bot
__device__ int   g_deg[NN];
__device__ float g_dinv[NN];
__device__ int   g_ptr[NN + 1];
__device__ int   g_cur[NN];
__device__ int   g_srcs[EMAX];

// ---------------- CSR build ------------------------------------------------
__global__ void k_zero_deg() {
    int i = blockIdx.x * blockDim.x + threadIdx.x;
    if (i < NN) g_deg[i] = 0;
}

__global__ void k_hist(const int* __restrict__ ei, int E) {
    int e = blockIdx.x * blockDim.x + threadIdx.x;
    if (e < E) atomicAdd(&g_deg[ei[E + e]], 1);   // dst row of edge_index
}

// single-block exclusive scan over 50000 degrees; also dinv = rsqrt(deg+1)
__global__ void k_scan() {
    __shared__ int s[1024];
    int t = threadIdx.x;
    const int CH = (NN + 1023) / 1024;            // 49
    int st = t * CH;
    int en = min(st + CH, NN);
    int sum = 0;
    for (int i = st; i < en; i++) sum += g_deg[i];
    s[t] = sum;
    __syncthreads();
    for (int off = 1; off < 1024; off <<= 1) {
        int v = (t >= off) ? s[t - off] : 0;
        __syncthreads();
        s[t] += v;
        __syncthreads();
    }
    int base = (t == 0) ? 0 : s[t - 1];
    for (int i = st; i < en; i++) {
        int d = g_deg[i];
        g_ptr[i] = base;
        g_cur[i] = base;
        g_dinv[i] = rsqrtf((float)(d + 1));       // +1 = self loop
        base += d;
    }
    if (t == 1023) g_ptr[NN] = base;
}

__global__ void k_fill(const int* __restrict__ ei, int E) {
    int e = blockIdx.x * blockDim.x + threadIdx.x;
    if (e < E) {
        int d = ei[E + e];
        int pos = atomicAdd(&g_cur[d], 1);
        if (pos < EMAX) g_srcs[pos] = ei[e];
    }
}

// ---------------- register-blocked GEMM (vectorized-k inner loop) ----------
// 64 rows x 128 cols per block, 256 threads, thread = 8 rows x 4 cols.
// k stepped by 4: per 4k = 12 LDS128 + 128 FFMA (91% FFMA issue slots).
#define GEMM_RB_SMEM ((HD * HD + 64 * HD) * 4)    // 64KB + 32KB

template <bool SCALE>
__global__ __launch_bounds__(256) void k_gemm_rb(
    const float* __restrict__ X, const float* __restrict__ W,
    float* __restrict__ Out)
{
    extern __shared__ float sm[];
    float* sW = sm;                 // 128x128
    float* sX = sm + HD * HD;       // 64x128
    int tid = threadIdx.x;

    float4* sW4 = (float4*)sW;
    const float4* W4 = (const float4*)W;
    for (int i = tid; i < HD * HD / 4; i += 256) sW4[i] = W4[i];

    int row0 = blockIdx.x * 64;
    int nr = min(64, NN - row0);
    const float4* X4 = (const float4*)(X + (size_t)row0 * HD);
    float4* sX4 = (float4*)sX;
    for (int i = tid; i < nr * (HD / 4); i += 256) sX4[i] = X4[i];
    __syncthreads();

    int tx = tid & 31;              // float4-col index (cols tx*4..tx*4+3)
    int rg = tid >> 5;              // row group 0..7 -> rows rg*8..rg*8+7
    const float4* xrow4 = sX4 + rg * 8 * 32;      // row-major, 32 float4/row

    float4 acc[8];
#pragma unroll
    for (int r = 0; r < 8; r++) acc[r] = make_float4(0.f, 0.f, 0.f, 0.f);

#pragma unroll 2
    for (int k4 = 0; k4 < 32; k4++) {
        float4 w0 = sW4[(4 * k4 + 0) * 32 + tx];
        float4 w1 = sW4[(4 * k4 + 1) * 32 + tx];
        float4 w2 = sW4[(4 * k4 + 2) * 32 + tx];
        float4 w3 = sW4[(4 * k4 + 3) * 32 + tx];
#pragma unroll
        for (int r = 0; r < 8; r++) {
            float4 xv = xrow4[r * 32 + k4];       // x[k..k+3] of row
            acc[r].x += xv.x * w0.x; acc[r].y += xv.x * w0.y;
            acc[r].z += xv.x * w0.z; acc[r].w += xv.x * w0.w;
            acc[r].x += xv.y * w1.x; acc[r].y += xv.y * w1.y;
            acc[r].z += xv.y * w1.z; acc[r].w += xv.y * w1.w;
            acc[r].x += xv.z * w2.x; acc[r].y += xv.z * w2.y;
            acc[r].z += xv.z * w2.z; acc[r].w += xv.z * w2.w;
            acc[r].x += xv.w * w3.x; acc[r].y += xv.w * w3.y;
            acc[r].z += xv.w * w3.z; acc[r].w += xv.w * w3.w;
        }
    }

#pragma unroll
    for (int r = 0; r < 8; r++) {
        int lrow = rg * 8 + r;
        if (lrow < nr) {
            int grow = row0 + lrow;
            float s = SCALE ? g_dinv[grow] : 1.0f;
            float4 v = make_float4(acc[r].x * s, acc[r].y * s,
                                   acc[r].z * s, acc[r].w * s);
            ((float4*)(Out + (size_t)grow * HD))[tx] = v;
        }
    }
}

// merged U/V GEMM: blockIdx.y picks Wh1 half / output buffer
__global__ __launch_bounds__(256) void k_gemm_uv(
    const float* __restrict__ X, const float* __restrict__ Wh1,
    float* __restrict__ U, float* __restrict__ V)
{
    extern __shared__ float sm[];
    float* sW = sm;
    float* sX = sm + HD * HD;
    int tid = threadIdx.x;
    const float* W = Wh1 + (size_t)blockIdx.y * HD * HD;
    float* Out = blockIdx.y ? V : U;

    float4* sW4 = (float4*)sW;
    const float4* W4 = (const float4*)W;
    for (int i = tid; i < HD * HD / 4; i += 256) sW4[i] = W4[i];

    int row0 = blockIdx.x * 64;
    int nr = min(64, NN - row0);
    const float4* X4 = (const float4*)(X + (size_t)row0 * HD);
    float4* sX4 = (float4*)sX;
    for (int i = tid; i < nr * (HD / 4); i += 256) sX4[i] = X4[i];
    __syncthreads();

    int tx = tid & 31;
    int rg = tid >> 5;
    const float4* xrow4 = sX4 + rg * 8 * 32;

    float4 acc[8];
#pragma unroll
    for (int r = 0; r < 8; r++) acc[r] = make_float4(0.f, 0.f, 0.f, 0.f);

#pragma unroll 2
    for (int k4 = 0; k4 < 32; k4++) {
        float4 w0 = sW4[(4 * k4 + 0) * 32 + tx];
        float4 w1 = sW4[(4 * k4 + 1) * 32 + tx];
        float4 w2 = sW4[(4 * k4 + 2) * 32 + tx];
        float4 w3 = sW4[(4 * k4 + 3) * 32 + tx];
#pragma unroll
        for (int r = 0; r < 8; r++) {
            float4 xv = xrow4[r * 32 + k4];
            acc[r].x += xv.x * w0.x; acc[r].y += xv.x * w0.y;
            acc[r].z += xv.x * w0.z; acc[r].w += xv.x * w0.w;
            acc[r].x += xv.y * w1.x; acc[r].y += xv.y * w1.y;
            acc[r].z += xv.y * w1.z; acc[r].w += xv.y * w1.w;
            acc[r].x += xv.z * w2.x; acc[r].y += xv.z * w2.y;
            acc[r].z += xv.z * w2.z; acc[r].w += xv.z * w2.w;
            acc[r].x += xv.w * w3.x; acc[r].y += xv.w * w3.y;
            acc[r].z += xv.w * w3.z; acc[r].w += xv.w * w3.w;
        }
    }

#pragma unroll
    for (int r = 0; r < 8; r++) {
        int lrow = rg * 8 + r;
        if (lrow < nr) {
            int grow = row0 + lrow;
            ((float4*)(Out + (size_t)grow * HD))[tx] = acc[r];
        }
    }
}

// ---------------- SpMM: warp per dst node, pull-based, no atomics ----------
// SRCSCALE=true : HS is raw X@W; gathered rows scaled by dinv[src] on the fly.
// SRCSCALE=false: HS already scaled by dinv (GEMM epilogue).
// Out[d] = relu( dinv[d] * (self + sum) + bias )
template <bool SRCSCALE>
__global__ __launch_bounds__(256) void k_spmm(
    const float* __restrict__ HS, const float* __restrict__ bias,
    float* __restrict__ Out)
{
    int gw = (blockIdx.x * blockDim.x + threadIdx.x) >> 5;
    int lane = threadIdx.x & 31;
    if (gw >= NN) return;

    float di = g_dinv[gw];
    const float4* hs4 = (const float4*)HS;
    float4 self = hs4[(size_t)gw * 32 + lane];
    float4 acc;
    if (SRCSCALE) {
        acc.x = self.x * di; acc.y = self.y * di;
        acc.z = self.z * di; acc.w = self.w * di;
    } else {
        acc = self;
    }
    int p0 = g_ptr[gw], p1 = g_ptr[gw + 1];

    int e = p0;
    for (; e + 32 <= p1; e += 32) {
        int idx = g_srcs[e + lane];
        float dv = SRCSCALE ? g_dinv[idx] : 0.f;
#pragma unroll
        for (int j = 0; j < 32; j++) {
            int s = __shfl_sync(0xffffffffu, idx, j);
            float4 v = hs4[(size_t)s * 32 + lane];
            if (SRCSCALE) {
                float ds = __shfl_sync(0xffffffffu, dv, j);
                acc.x = fmaf(v.x, ds, acc.x);
                acc.y = fmaf(v.y, ds, acc.y);
                acc.z = fmaf(v.z, ds, acc.z);
                acc.w = fmaf(v.w, ds, acc.w);
            } else {
                acc.x += v.x; acc.y += v.y; acc.z += v.z; acc.w += v.w;
            }
        }
    }
    if (e < p1) {
        int m = p1 - e;
        int idx = (lane < m) ? g_srcs[e + lane] : 0;
        float dv = SRCSCALE ? ((lane < m) ? g_dinv[idx] : 0.f) : 0.f;
        for (int j = 0; j < m; j++) {
            int s = __shfl_sync(0xffffffffu, idx, j);
            float4 v = hs4[(size_t)s * 32 + lane];
            if (SRCSCALE) {
                float ds = __shfl_sync(0xffffffffu, dv, j);
                acc.x = fmaf(v.x, ds, acc.x);
                acc.y = fmaf(v.y, ds, acc.y);
                acc.z = fmaf(v.z, ds, acc.z);
                acc.w = fmaf(v.w, ds, acc.w);
            } else {
                acc.x += v.x; acc.y += v.y; acc.z += v.z; acc.w += v.w;
            }
        }
    }

    float4 b = ((const float4*)bias)[lane];
    float4 o;
    o.x = fmaxf(fmaf(acc.x, di, b.x), 0.f);
    o.y = fmaxf(fmaf(acc.y, di, b.y), 0.f);
    o.z = fmaxf(fmaf(acc.z, di, b.z), 0.f);
    o.w = fmaxf(fmaf(acc.w, di, b.w), 0.f);
    ((float4*)Out)[(size_t)gw * 32 + lane] = o;
}

// ---------------- pair epilogue --------------------------------------------
// out[p] = relu(U[p0] + V[p1] + bh1) . Wh2 + bh2
__global__ __launch_bounds__(256) void k_pair(
    const int* __restrict__ pairs,
    const float* __restrict__ bh1, const float* __restrict__ Wh2,
    const float* __restrict__ bh2,
    float* __restrict__ out, int P)
{
    int gw = (blockIdx.x * blockDim.x + threadIdx.x) >> 5;
    int lane = threadIdx.x & 31;
    if (gw >= P) return;

    int n0 = pairs[2 * gw];
    int n1 = pairs[2 * gw + 1];

    const float4* U4 = (const float4*)g_bufU;
    const float4* V4 = (const float4*)g_bufV;
    float4 u = U4[(size_t)n0 * 32 + lane];
    float4 v = V4[(size_t)n1 * 32 + lane];
    float4 b = ((const float4*)bh1)[lane];
    float4 w = ((const float4*)Wh2)[lane];

    float s = fmaxf(u.x + v.x + b.x, 0.f) * w.x
            + fmaxf(u.y + v.y + b.y, 0.f) * w.y
            + fmaxf(u.z + v.z + b.z, 0.f) * w.z
            + fmaxf(u.w + v.w + b.w, 0.f) * w.w;
#pragma unroll
    for (int o = 16; o > 0; o >>= 1)
        s += __shfl_xor_sync(0xffffffffu, s, o);
    if (lane == 0) out[gw] = s + bh2[0];
}

// ---------------- launch ---------------------------------------------------
extern "C" void kernel_launch(void* const* d_in, const int* in_sizes, int n_in,
                              void* d_out, int out_size)
{
    const float* x    = (const float*)d_in[0];
    const int*   ei   = (const int*)d_in[1];
    const int*   prs  = (const int*)d_in[2];
    const float* W1   = (const float*)d_in[3];
    const float* b1   = (const float*)d_in[4];
    const float* W2   = (const float*)d_in[5];
    const float* b2   = (const float*)d_in[6];
    const float* Wh1  = (const float*)d_in[7];
    const float* bh1  = (const float*)d_in[8];
    const float* Wh2  = (const float*)d_in[9];
    const float* bh2  = (const float*)d_in[10];
    float* out = (float*)d_out;

    int E = in_sizes[1] / 2;
    int P = in_sizes[2] / 2;

    // one-time host objects (no device memory involved)
    static cudaStream_t s2 = []() {
        cudaStream_t s;
        cudaStreamCreateWithFlags(&s, cudaStreamNonBlocking);
        return s;
    }();
    static cudaEvent_t evFork = []() {
        cudaEvent_t e;
        cudaEventCreateWithFlags(&e, cudaEventDisableTiming);
        return e;
    }();
    static cudaEvent_t evJoin = []() {
        cudaEvent_t e;
        cudaEventCreateWithFlags(&e, cudaEventDisableTiming);
        return e;
    }();

    cudaFuncSetAttribute(k_gemm_rb<true>,
                         cudaFuncAttributeMaxDynamicSharedMemorySize, GEMM_RB_SMEM);
    cudaFuncSetAttribute(k_gemm_rb<false>,
                         cudaFuncAttributeMaxDynamicSharedMemorySize, GEMM_RB_SMEM);
    cudaFuncSetAttribute(k_gemm_uv,
                         cudaFuncAttributeMaxDynamicSharedMemorySize, GEMM_RB_SMEM);

    void *pA = nullptr, *pB = nullptr, *pU = nullptr, *pV = nullptr;
    cudaGetSymbolAddress(&pA, g_bufA);
    cudaGetSymbolAddress(&pB, g_bufB);
    cudaGetSymbolAddress(&pU, g_bufU);
    cudaGetSymbolAddress(&pV, g_bufV);
    float* A = (float*)pA;
    float* B = (float*)pB;
    float* U = (float*)pU;
    float* V = (float*)pV;

    const int GB = (NN + 63) / 64;

    // fork: CSR build chain on s2, concurrent with GEMM1 on main stream.
    // Launch-call order keeps the GEMM at position 4 so ncu's fixed window
    // profiles the (new) GEMM.
    cudaEventRecord(evFork, 0);
    cudaStreamWaitEvent(s2, evFork, 0);

    k_zero_deg<<<(NN + 255) / 256, 256, 0, s2>>>();
    k_hist<<<(E + 255) / 256, 256, 0, s2>>>(ei, E);
    k_scan<<<1, 1024, 0, s2>>>();

    // GEMM1 (raw X@W1 — no dinv dependency, overlaps CSR build)
    k_gemm_rb<false><<<GB, 256, GEMM_RB_SMEM>>>(x, W1, A);

    k_fill<<<(E + 255) / 256, 256, 0, s2>>>(ei, E);

    // join
    cudaEventRecord(evJoin, s2);
    cudaStreamWaitEvent(0, evJoin, 0);

    // layer 1 aggregation: dinv[src] applied at gather time
    k_spmm<true><<<(NN * 32 + 255) / 256, 256>>>(A, b1, B);
    // layer 2
    k_gemm_rb<true><<<GB, 256, GEMM_RB_SMEM>>>(B, W2, A);
    k_spmm<false><<<(NN * 32 + 255) / 256, 256>>>(A, b2, B);
    // factored pair-MLP head: U and V in one launch
    dim3 guv(GB, 2);
    k_gemm_uv<<<guv, 256, GEMM_RB_SMEM>>>(B, Wh1, U, V);
    // pair epilogue
    k_pair<<<(P * 32 + 255) / 256, 256>>>(prs, bh1, Wh2, bh2, out, P);
}